// round 10
// baseline (speedup 1.0000x reference)
#include <cuda_runtime.h>
#include <cstdint>
#include <cstddef>

// ---------------- problem constants ----------------
#define E_EXPERTS 64
#define TPE       1024
#define KDIM      1024
#define NDIM      2048
#define NTILES    8192                  // (NDIM/BN)*(TPE/BM)*E = 16*8*64
#define NCTAS     304                   // 2 CTAs/SM x 152 SMs (GB300)

// ---------------- tiling ----------------
#define BM 128
#define BN 128
#define BK 32
#define NKT (KDIM / BK)                 // 32 K-tiles per output tile

#define A_STAGE_BYTES (BM * BK * 4)     // 16384
#define B_STAGE_BYTES (BN * BK * 4)     // 16384
#define STAGE_BYTES (A_STAGE_BYTES + B_STAGE_BYTES)   // 32768
#define NSTAGES 3
#define SM_STAGE0   1024
#define SMEM_BYTES (SM_STAGE0 + NSTAGES * STAGE_BYTES)   // 99328 -> 2 CTAs/SM

#define NTHREADS 128

__device__ __forceinline__ uint32_t smem_u32(const void* p) {
    uint32_t a;
    asm("{ .reg .u64 t; cvta.to.shared.u64 t, %1; cvt.u32.u64 %0, t; }" : "=r"(a) : "l"(p));
    return a;
}
__device__ __forceinline__ void cp16(uint32_t dst, const float* src) {
    asm volatile("cp.async.cg.shared.global [%0], [%1], 16;" :: "r"(dst), "l"(src));
}
__device__ __forceinline__ unsigned lds32(uint32_t addr) {
    unsigned v;
    asm volatile("ld.shared.b32 %0, [%1];" : "=r"(v) : "r"(addr));
    return v;
}

#define MBARRIER_INIT(mb, c) \
    asm volatile("mbarrier.init.shared.b64 [%0], %1;" :: "r"((uint32_t)(mb)), "r"((uint32_t)(c)) : "memory")
#define MBARRIER_ARRIVE(mb) \
    asm volatile("mbarrier.arrive.shared.b64 _, [%0];" :: "r"((uint32_t)(mb)) : "memory")
// .noinc: async completion consumes the preset expected count (init NTHREADS).
#define CP_MBARRIER_ARRIVE_NOINC(mb) \
    asm volatile("cp.async.mbarrier.arrive.noinc.shared.b64 [%0];" :: "r"((uint32_t)(mb)) : "memory")

__device__ __forceinline__ void mbar_wait(uint32_t mb, uint32_t parity) {
    uint32_t done;
    asm volatile(
        "{ .reg .pred p; mbarrier.try_wait.parity.acquire.cta.shared::cta.b64 p, [%1], %2; selp.b32 %0, 1, 0, p; }"
        : "=r"(done) : "r"(mb), "r"(parity) : "memory");
    if (!done) {
        asm volatile(
            "{ .reg .pred P1;\n"
            "WL_%=: mbarrier.try_wait.parity.acquire.cta.shared::cta.b64 P1, [%0], %1, 0x989680;\n"
            "@P1 bra.uni WD_%=;\n"
            "bra.uni WL_%=;\n"
            "WD_%=: }"
            :: "r"(mb), "r"(parity) : "memory");
    }
}

__global__ __launch_bounds__(NTHREADS, 2)
void moe_persistent_tf32(const float* __restrict__ x,
                         const float* __restrict__ w,
                         float* __restrict__ out)
{
    extern __shared__ char sm[];
    const uint32_t sbase = smem_u32(sm);

    const int tid  = threadIdx.x;
    const int lane = tid & 31;
    const int warp = tid >> 5;
    const int wm   = warp >> 1;          // 0..1 (64 rows)
    const int wn   = warp & 1;           // 0..1 (64 cols)
    const int r    = lane >> 2;          // 0..7
    const int la3  = lane & 3;           // 0..3

    const int bid = blockIdx.x;
    const int G   = gridDim.x;

    // mbarriers: full(s) = sbase + s*16, empty(s) = sbase + s*16 + 8
    if (tid == 0) {
        #pragma unroll
        for (int s = 0; s < NSTAGES; s++) {
            MBARRIER_INIT(sbase + s * 16,     NTHREADS);   // full
            MBARRIER_INIT(sbase + s * 16 + 8, NTHREADS);   // empty
        }
    }
    __syncthreads();

    // ---- cp.async per-thread geometry ----
    // A stage: [m=128][k=32] 128B rows, granule swizzle kq^(row&7).
    // B stage: [k=32][n=128] 512B rows, granule swizzle n4^((k&3)<<1).
    const int arow0 = tid >> 3, akq = tid & 7;
    const int bk0   = tid >> 5, bn4 = tid & 31;
    const uint32_t aDst0 = (uint32_t)(SM_STAGE0 + arow0 * 128 + ((akq ^ (arow0 & 7)) << 4));
    const uint32_t bDst0 = (uint32_t)(SM_STAGE0 + A_STAGE_BYTES + bk0 * 512 + ((bn4 ^ ((bk0 & 3) << 1)) << 4));

    // produce K-tile for global production index p (rolls across output tiles)
    auto produce = [&](int p, int slot) {
        const int tile_id = bid + (p >> 5) * G;
        const int kt = p & 31;
        const int e  = tile_id >> 7;
        const int by = (tile_id >> 4) & 7;
        const int bx = tile_id & 15;
        const float* as = x + (size_t)((e << 10) + (by << 7) + arow0) * KDIM
                            + (kt << 5) + (akq << 2);
        const float* bs = w + ((size_t)e << 21)
                            + (size_t)((kt << 5) + bk0) * NDIM + (bx << 7) + (bn4 << 2);
        const uint32_t sb = sbase + (uint32_t)slot * STAGE_BYTES;
        #pragma unroll
        for (int i = 0; i < 8; i++)
            cp16(sb + aDst0 + i * 2048, as + (size_t)i * 16 * KDIM);
        #pragma unroll
        for (int i = 0; i < 8; i++)
            cp16(sb + bDst0 + i * 2048, bs + (size_t)i * 4 * NDIM);
        CP_MBARRIER_ARRIVE_NOINC(sbase + slot * 16);   // full(slot) on completion
    };

    // ---- fragment address precompute ----
    const uint32_t AbaseRel = (uint32_t)(SM_STAGE0 + (wm * 64 + r) * 128 + la3 * 4);
    const uint32_t BbaseRel = (uint32_t)(SM_STAGE0 + A_STAGE_BYTES + la3 * 512);
    uint32_t bco[8];
    #pragma unroll
    for (int nf = 0; nf < 8; nf++) {
        int g = (wn * 16 + nf * 2 + (r >> 2)) ^ (la3 << 1);
        bco[nf] = (uint32_t)((g << 4) + (r & 3) * 4);
    }

    const int n_tiles = (NTILES - bid + G - 1) / G;
    const int total   = n_tiles * NKT;

    float acc[4][8][4];
    #pragma unroll
    for (int mf = 0; mf < 4; mf++)
        #pragma unroll
        for (int nf = 0; nf < 8; nf++)
            #pragma unroll
            for (int q = 0; q < 4; q++)
                acc[mf][nf][q] = 0.0f;

    // ---- cursors ----
    int pslot = 0, pphase = 1;   // producer starts parity 1 (empty-waits pass)
    int cslot = 0, cphase = 0;
    int p = 0;

    // prologue: 2 stages in flight (every CTA has >= 26 tiles, so total >= 2)
    #pragma unroll
    for (int j = 0; j < 2; j++) {
        mbar_wait(sbase + pslot * 16 + 8, (uint32_t)pphase);
        produce(p++, pslot);
        if (++pslot == NSTAGES) { pslot = 0; pphase ^= 1; }
    }

    for (int g = 0; g < total; ++g) {
        mbar_wait(sbase + cslot * 16, (uint32_t)cphase);       // full(cslot)

        const uint32_t As = sbase + (uint32_t)cslot * STAGE_BYTES + AbaseRel;
        const uint32_t Bs = sbase + (uint32_t)cslot * STAGE_BYTES + BbaseRel;

        #pragma unroll
        for (int kk = 0; kk < 4; ++kk) {
            const uint32_t xo0 = (uint32_t)(((2 * kk + 0) ^ r) << 4);
            const uint32_t xo1 = (uint32_t)(((2 * kk + 1) ^ r) << 4);
            const uint32_t bko = (uint32_t)(kk * 4096);

            // Raw fp32 bits as tf32 operands (HW truncates mantissa).
            unsigned a[4][4], b[8][2];
            #pragma unroll
            for (int mf = 0; mf < 4; mf++) {
                uint32_t base = As + (uint32_t)(mf * 2048);
                a[mf][0] = lds32(base + xo0);
                a[mf][1] = lds32(base + 1024 + xo0);
                a[mf][2] = lds32(base + xo1);
                a[mf][3] = lds32(base + 1024 + xo1);
            }
            #pragma unroll
            for (int nf = 0; nf < 8; nf++) {
                uint32_t base = Bs + bko + bco[nf];
                b[nf][0] = lds32(base);
                b[nf][1] = lds32(base + 2048);
            }
            #pragma unroll
            for (int mf = 0; mf < 4; mf++)
                #pragma unroll
                for (int nf = 0; nf < 8; nf++) {
                    asm volatile(
                        "mma.sync.aligned.m16n8k8.row.col.f32.tf32.tf32.f32 "
                        "{%0,%1,%2,%3}, {%4,%5,%6,%7}, {%8,%9}, {%0,%1,%2,%3};\n"
                        : "+f"(acc[mf][nf][0]), "+f"(acc[mf][nf][1]),
                          "+f"(acc[mf][nf][2]), "+f"(acc[mf][nf][3])
                        : "r"(a[mf][0]), "r"(a[mf][1]), "r"(a[mf][2]), "r"(a[mf][3]),
                          "r"(b[nf][0]), "r"(b[nf][1]));
                }
        }

        MBARRIER_ARRIVE(sbase + cslot * 16 + 8);               // empty(cslot)
        if (++cslot == NSTAGES) { cslot = 0; cphase ^= 1; }

        // keep the ring rolling across tile boundaries
        if (p < total) {
            mbar_wait(sbase + pslot * 16 + 8, (uint32_t)pphase);
            produce(p++, pslot);
            if (++pslot == NSTAGES) { pslot = 0; pphase ^= 1; }
        }

        // end of an output tile: epilogue (overlaps next tile's in-flight loads)
        if ((g & 31) == 31) {
            const int tile_id = bid + (g >> 5) * G;
            const int e  = tile_id >> 7;
            const int by = (tile_id >> 4) & 7;
            const int bx = tile_id & 15;
            float* outT = out + (size_t)((e << 10) + (by << 7)) * NDIM + (bx << 7);
            #pragma unroll
            for (int mf = 0; mf < 4; mf++) {
                int r0 = wm * 64 + mf * 16 + r;
                float* o0 = outT + (size_t)r0 * NDIM;
                float* o1 = outT + (size_t)(r0 + 8) * NDIM;
                #pragma unroll
                for (int nf = 0; nf < 8; nf++) {
                    int c = wn * 64 + nf * 8 + 2 * la3;
                    __stcs(reinterpret_cast<float2*>(o0 + c),
                           make_float2(acc[mf][nf][0], acc[mf][nf][1]));
                    __stcs(reinterpret_cast<float2*>(o1 + c),
                           make_float2(acc[mf][nf][2], acc[mf][nf][3]));
                    acc[mf][nf][0] = 0.0f; acc[mf][nf][1] = 0.0f;
                    acc[mf][nf][2] = 0.0f; acc[mf][nf][3] = 0.0f;
                }
            }
        }
    }
}

extern "C" void kernel_launch(void* const* d_in, const int* in_sizes, int n_in,
                              void* d_out, int out_size)
{
    (void)in_sizes; (void)n_in; (void)out_size;
    const float* x = (const float*)d_in[0];
    // d_in[1] = expert_size (equal splits guaranteed by setup)
    const float* w = (const float*)d_in[2];
    float* out = (float*)d_out;

    cudaFuncSetAttribute(moe_persistent_tf32,
                         cudaFuncAttributeMaxDynamicSharedMemorySize, SMEM_BYTES);

    moe_persistent_tf32<<<NCTAS, NTHREADS, SMEM_BYTES>>>(x, w, out);
}

// round 13
// speedup vs baseline: 1.4123x; 1.4123x over previous
#include <cuda_runtime.h>
#include <cuda_fp16.h>
#include <cstdint>
#include <cstddef>

// ---------------- problem constants ----------------
#define E_EXPERTS 64
#define TPE       1024
#define KDIM      1024
#define NDIM      2048

// ---------------- tiling ----------------
#define BM 128
#define BN 128
#define BK 32
#define NKT (KDIM / BK)                 // 32 K-tiles

// fp16 stage: A 128m x 32k x 2B = 8KB, B same
#define A_STAGE_BYTES 8192
#define STAGE_BYTES   16384
#define NSTAGES 6
#define LEAD    (NSTAGES - 1)
#define SM_STAGE0 1024
#define SMEM_BYTES (SM_STAGE0 + NSTAGES * STAGE_BYTES)   // 99328 -> 2 CTAs/SM
#define NTHREADS 128

// ---------------- fp16 scratch as uint4 (16B-aligned) ----------------
// Image = 8KB = 512 uint4. xh image (e,by,kt): granule g=(mb*16+k2)*2+h,
// word j = half2{ x[m][2k2], x[m][2k2+1] }, m = mb*8+h*4+j (local 0..127).
// wh image (e,bx,kt): granule g=(n8*16+k2)*2+h,
// word j = half2{ w[2k2][n], w[2k2+1][n] }, n = n8*8+h*4+j (local 0..127).
__device__ uint4 g_xh4[(size_t)E_EXPERTS * 8  * NKT * 512];   // 128 MB
__device__ uint4 g_wh4[(size_t)E_EXPERTS * 16 * NKT * 512];   // 256 MB

__device__ __forceinline__ uint32_t smem_u32(const void* p) {
    uint32_t a;
    asm("{ .reg .u64 t; cvta.to.shared.u64 t, %1; cvt.u32.u64 %0, t; }" : "=r"(a) : "l"(p));
    return a;
}
__device__ __forceinline__ void cp16(uint32_t dst, const uint4* src) {
    asm volatile("cp.async.cg.shared.global [%0], [%1], 16;" :: "r"(dst), "l"(src));
}
__device__ __forceinline__ unsigned lds32(uint32_t addr) {
    unsigned v;
    asm volatile("ld.shared.b32 %0, [%1];" : "=r"(v) : "r"(addr));
    return v;
}
__device__ __forceinline__ unsigned pack2(float lo, float hi) {
    __half2 h = __floats2half2_rn(lo, hi);
    return *reinterpret_cast<unsigned*>(&h);
}

#define MBARRIER_INIT(mb, c) \
    asm volatile("mbarrier.init.shared.b64 [%0], %1;" :: "r"((uint32_t)(mb)), "r"((uint32_t)(c)) : "memory")
#define MBARRIER_ARRIVE(mb) \
    asm volatile("mbarrier.arrive.shared.b64 _, [%0];" :: "r"((uint32_t)(mb)) : "memory")
#define CP_MBARRIER_ARRIVE_NOINC(mb) \
    asm volatile("cp.async.mbarrier.arrive.noinc.shared.b64 [%0];" :: "r"((uint32_t)(mb)) : "memory")

__device__ __forceinline__ void mbar_wait(uint32_t mb, uint32_t parity) {
    uint32_t done;
    asm volatile(
        "{ .reg .pred p; mbarrier.try_wait.parity.acquire.cta.shared::cta.b64 p, [%1], %2; selp.b32 %0, 1, 0, p; }"
        : "=r"(done) : "r"(mb), "r"(parity) : "memory");
    if (!done) {
        asm volatile(
            "{ .reg .pred P1;\n"
            "WL_%=: mbarrier.try_wait.parity.acquire.cta.shared::cta.b64 P1, [%0], %1, 0x989680;\n"
            "@P1 bra.uni WD_%=;\n"
            "bra.uni WL_%=;\n"
            "WD_%=: }"
            :: "r"(mb), "r"(parity) : "memory");
    }
}

// ============ pre-pass: x -> xh (tiled transpose to k-pair images) ============
__global__ __launch_bounds__(128)
void prep_x(const float* __restrict__ x)
{
    __shared__ float sx[128 * 33];      // [m][k] padded
    const int img = blockIdx.x;         // (e*8+by)*32 + kt
    const int tid = threadIdx.x;
    const int row0 = (img >> 5) * 128;
    const int col0 = (img & 31) * 32;

    #pragma unroll
    for (int t = 0; t < 8; t++) {
        int q = tid + t * 128;          // 1024 float4 slots
        int m = q >> 3, c4 = q & 7;
        float4 v = *reinterpret_cast<const float4*>(x + (size_t)(row0 + m) * KDIM + col0 + c4 * 4);
        sx[m * 33 + c4 * 4 + 0] = v.x;
        sx[m * 33 + c4 * 4 + 1] = v.y;
        sx[m * 33 + c4 * 4 + 2] = v.z;
        sx[m * 33 + c4 * 4 + 3] = v.w;
    }
    __syncthreads();

    uint4* outp = g_xh4 + (size_t)img * 512;
    #pragma unroll
    for (int i = 0; i < 4; i++) {
        int g = tid + i * 128;          // 512 granules; g = (mb*16+k2)*2+h
        int h = g & 1, k2 = (g >> 1) & 15, mb = g >> 5;
        uint4 o;
        unsigned ow[4];
        #pragma unroll
        for (int j = 0; j < 4; j++) {
            int m = mb * 8 + h * 4 + j;
            ow[j] = pack2(sx[m * 33 + 2 * k2], sx[m * 33 + 2 * k2 + 1]);
        }
        o.x = ow[0]; o.y = ow[1]; o.z = ow[2]; o.w = ow[3];
        outp[g] = o;
    }
}

// ============ pre-pass: w -> wh (k-pair interleave images) ============
__global__ __launch_bounds__(128)
void prep_w(const float* __restrict__ w)
{
    const int img = blockIdx.x;         // (e*16+bx)*32 + kt
    const int tid = threadIdx.x;
    const int kt = img & 31;
    const int bx = (img >> 5) & 15;
    const int e  = img >> 9;
    const float* wb = w + (size_t)e * KDIM * NDIM + (size_t)(kt * 32) * NDIM + bx * 128;
    uint4* outp = g_wh4 + (size_t)img * 512;

    #pragma unroll
    for (int i = 0; i < 4; i++) {
        int gIn = tid + i * 128;        // n fastest for coalesced reads
        int k2 = gIn >> 5, n8 = (gIn >> 1) & 15, h = gIn & 1;
        int n = n8 * 8 + h * 4;
        float4 r0 = *reinterpret_cast<const float4*>(wb + (size_t)(2 * k2) * NDIM + n);
        float4 r1 = *reinterpret_cast<const float4*>(wb + (size_t)(2 * k2 + 1) * NDIM + n);
        uint4 o;
        o.x = pack2(r0.x, r1.x);
        o.y = pack2(r0.y, r1.y);
        o.z = pack2(r0.z, r1.z);
        o.w = pack2(r0.w, r1.w);
        outp[(n8 * 16 + k2) * 2 + h] = o;
    }
}

// ============ main GEMM: fp16 mma.sync m16n8k16, mbarrier ring ============
__global__ __launch_bounds__(NTHREADS, 2)
void moe_fp16_v8(float* __restrict__ out)
{
    extern __shared__ char sm[];
    const uint32_t sbase = smem_u32(sm);

    const int tid  = threadIdx.x;
    const int lane = tid & 31;
    const int warp = tid >> 5;
    const int wm   = warp >> 1;          // 0..1 (64 rows)
    const int wn   = warp & 1;           // 0..1 (64 cols)
    const int r    = lane >> 2;          // 0..7
    const int la3  = lane & 3;           // 0..3

    const int bx = blockIdx.x;           // 0..15
    const int by = blockIdx.y;           // 0..7
    const int e  = blockIdx.z;

    if (tid == 0) {
        #pragma unroll
        for (int s = 0; s < NSTAGES; s++) {
            MBARRIER_INIT(sbase + s * 16,     NTHREADS);   // full
            MBARRIER_INIT(sbase + s * 16 + 8, NTHREADS);   // empty
        }
    }
    __syncthreads();

    const uint4* aImg = g_xh4 + (size_t)((e * 8  + by) * 32) * 512;
    const uint4* bImg = g_wh4 + (size_t)((e * 16 + bx) * 32) * 512;

    auto produce = [&](int kt, int slot) {
        const uint32_t sb = sbase + SM_STAGE0 + (uint32_t)slot * STAGE_BYTES;
        const uint4* as = aImg + (size_t)kt * 512 + tid;
        const uint4* bs = bImg + (size_t)kt * 512 + tid;
        #pragma unroll
        for (int i = 0; i < 4; i++)
            cp16(sb + tid * 16 + i * 2048, as + i * 128);
        #pragma unroll
        for (int i = 0; i < 4; i++)
            cp16(sb + A_STAGE_BYTES + tid * 16 + i * 2048, bs + i * 128);
        CP_MBARRIER_ARRIVE_NOINC(sbase + slot * 16);
    };

    // fragment bases — NOTE: sbase INCLUDED (missing sbase was the R11/R12 NaN bug)
    // addr(m,k2) = (m>>3)*512 + k2*32 + ((m>>2)&1)*16 + (m&3)*4; m_low=r -> +r*4.
    const uint32_t aTh = sbase + (uint32_t)(SM_STAGE0 + (wm * 8) * 512 + la3 * 32 + r * 4);
    const uint32_t bTh = sbase + (uint32_t)(SM_STAGE0 + A_STAGE_BYTES + (wn * 8) * 512 + la3 * 32 + r * 4);

    float acc[4][8][4];
    #pragma unroll
    for (int mf = 0; mf < 4; mf++)
        #pragma unroll
        for (int nf = 0; nf < 8; nf++)
            #pragma unroll
            for (int q = 0; q < 4; q++)
                acc[mf][nf][q] = 0.0f;

    int pslot = 0, pphase = 1;
    int cslot = 0, cphase = 0;

    #pragma unroll
    for (int j = 0; j < LEAD; j++) {
        mbar_wait(sbase + pslot * 16 + 8, (uint32_t)pphase);
        produce(j, pslot);
        if (++pslot == NSTAGES) { pslot = 0; pphase ^= 1; }
    }

    for (int kt = 0; kt < NKT; ++kt) {
        mbar_wait(sbase + cslot * 16, (uint32_t)cphase);

        const uint32_t As = aTh + (uint32_t)cslot * STAGE_BYTES;
        const uint32_t Bs = bTh + (uint32_t)cslot * STAGE_BYTES;

        #pragma unroll
        for (int kk = 0; kk < 2; ++kk) {            // two k16 steps
            const uint32_t ko = (uint32_t)(kk * 256);   // k2 += 8

            unsigned a[4][4], b[8][2];
            #pragma unroll
            for (int mf = 0; mf < 4; mf++) {
                uint32_t base = As + ko + (uint32_t)(mf * 1024);
                a[mf][0] = lds32(base);              // (m, k2)
                a[mf][1] = lds32(base + 512);        // m+8
                a[mf][2] = lds32(base + 128);        // k2+4
                a[mf][3] = lds32(base + 640);        // m+8, k2+4
            }
            #pragma unroll
            for (int nf = 0; nf < 8; nf++) {
                uint32_t base = Bs + ko + (uint32_t)(nf * 512);
                b[nf][0] = lds32(base);              // (n, k2)
                b[nf][1] = lds32(base + 128);        // k2+4
            }
            #pragma unroll
            for (int mf = 0; mf < 4; mf++)
                #pragma unroll
                for (int nf = 0; nf < 8; nf++) {
                    asm volatile(
                        "mma.sync.aligned.m16n8k16.row.col.f32.f16.f16.f32 "
                        "{%0,%1,%2,%3}, {%4,%5,%6,%7}, {%8,%9}, {%0,%1,%2,%3};\n"
                        : "+f"(acc[mf][nf][0]), "+f"(acc[mf][nf][1]),
                          "+f"(acc[mf][nf][2]), "+f"(acc[mf][nf][3])
                        : "r"(a[mf][0]), "r"(a[mf][1]), "r"(a[mf][2]), "r"(a[mf][3]),
                          "r"(b[nf][0]), "r"(b[nf][1]));
                }
        }

        MBARRIER_ARRIVE(sbase + cslot * 16 + 8);
        if (++cslot == NSTAGES) { cslot = 0; cphase ^= 1; }

        if (kt + LEAD < NKT) {
            mbar_wait(sbase + pslot * 16 + 8, (uint32_t)pphase);
            produce(kt + LEAD, pslot);
            if (++pslot == NSTAGES) { pslot = 0; pphase ^= 1; }
        }
    }

    // ---- epilogue: 64x64 warp tile ----
    float* outT = out + (size_t)(e * TPE + by * BM) * NDIM + (size_t)bx * BN;
    #pragma unroll
    for (int mf = 0; mf < 4; mf++) {
        int r0 = wm * 64 + mf * 16 + r;
        float* o0 = outT + (size_t)r0 * NDIM;
        float* o1 = outT + (size_t)(r0 + 8) * NDIM;
        #pragma unroll
        for (int nf = 0; nf < 8; nf++) {
            int c = wn * 64 + nf * 8 + 2 * la3;
            *reinterpret_cast<float2*>(o0 + c) = make_float2(acc[mf][nf][0], acc[mf][nf][1]);
            *reinterpret_cast<float2*>(o1 + c) = make_float2(acc[mf][nf][2], acc[mf][nf][3]);
        }
    }
}

extern "C" void kernel_launch(void* const* d_in, const int* in_sizes, int n_in,
                              void* d_out, int out_size)
{
    (void)in_sizes; (void)n_in; (void)out_size;
    const float* x = (const float*)d_in[0];
    // d_in[1] = expert_size (equal splits guaranteed by setup)
    const float* w = (const float*)d_in[2];
    float* out = (float*)d_out;

    prep_x<<<E_EXPERTS * 8 * NKT, 128>>>(x);        // 16384 blocks
    prep_w<<<E_EXPERTS * 16 * NKT, 128>>>(w);       // 32768 blocks

    cudaFuncSetAttribute(moe_fp16_v8,
                         cudaFuncAttributeMaxDynamicSharedMemorySize, SMEM_BYTES);
    dim3 grid(NDIM / BN, TPE / BM, E_EXPERTS);      // (16, 8, 64)
    moe_fp16_v8<<<grid, NTHREADS, SMEM_BYTES>>>(out);
}